// round 10
// baseline (speedup 1.0000x reference)
#include <cuda_runtime.h>
#include <stdint.h>
#include <math.h>

#define T_SEQ  2048
#define NBATCH 2
#define DIM    1024
#define HEADS  8
#define NKEYS  256
#define TOPK   32
#define DHEAD  128

// bf16 stored as raw uint16 — no cuda_bf16.h anywhere.
typedef unsigned short u16;

__device__ __forceinline__ u16 f2b(float v) {
    const uint32_t u = __float_as_uint(v);
    return (u16)((u + 0x7fffu + ((u >> 16) & 1u)) >> 16);   // round-nearest-even
}
__device__ __forceinline__ float b2f(u16 h) {
    return __uint_as_float(((uint32_t)h) << 16);
}

// ---------------- scratch (static device globals; no allocation) ----------------
__device__ __align__(16) u16 g_xhi [(size_t)NBATCH * T_SEQ * DIM];
__device__ __align__(16) u16 g_xlo [(size_t)NBATCH * T_SEQ * DIM];
__device__ __align__(16) u16 g_wqhi[(size_t)2 * DIM * DIM];
__device__ __align__(16) u16 g_wqlo[(size_t)2 * DIM * DIM];
__device__ __align__(16) u16 g_wohi[(size_t)DIM * DIM];
__device__ __align__(16) u16 g_wolo[(size_t)DIM * DIM];
__device__ __align__(16) u16 g_khi [(size_t)16 * NKEYS * DHEAD];   // [zk=h*2+p][n][d]
__device__ __align__(16) u16 g_klo [(size_t)16 * NKEYS * DHEAD];
__device__ __align__(16) u16 g_qhi [(size_t)NBATCH * T_SEQ * 2 * DIM];
__device__ __align__(16) u16 g_qlo [(size_t)NBATCH * T_SEQ * 2 * DIM];
__device__ __align__(16) u16 g_ahi [(size_t)NBATCH * T_SEQ * DIM];  // attn pre-Wo
__device__ __align__(16) u16 g_alo [(size_t)NBATCH * T_SEQ * DIM];
__device__ float g_dots[(size_t)32 * T_SEQ * NKEYS];   // (z = b*16+h*2+p, t, n)
__device__ float g_s1s [(size_t)32 * T_SEQ * TOPK];
__device__ int   g_s1i [(size_t)32 * T_SEQ * TOPK];

// ---------------- tensor-core primitives ----------------
__device__ __forceinline__ void ldsm4(uint32_t* r, uint32_t a) {
    asm volatile("ldmatrix.sync.aligned.m8n8.x4.shared.b16 {%0,%1,%2,%3}, [%4];"
        : "=r"(r[0]), "=r"(r[1]), "=r"(r[2]), "=r"(r[3]) : "r"(a));
}
__device__ __forceinline__ void mma16(float* c, const uint32_t* a, const uint32_t* b) {
    asm volatile("mma.sync.aligned.m16n8k16.row.col.f32.bf16.bf16.f32 "
        "{%0,%1,%2,%3},{%4,%5,%6,%7},{%8,%9},{%0,%1,%2,%3};"
        : "+f"(c[0]), "+f"(c[1]), "+f"(c[2]), "+f"(c[3])
        : "r"(a[0]), "r"(a[1]), "r"(a[2]), "r"(a[3]), "r"(b[0]), "r"(b[1]));
}

// ---------------- bf16x3 split GEMM: C = A(MxK) * B(NxK)^T ----------------
// Block tile 128x128, BK=32, 256 threads (8 warps as 4m x 2n, warp tile 32x64).
// Fragments via ldmatrix.x4 (12 loads per 48 MMAs).
#define PAD 40

template<bool SPLIT_OUT, bool BIAS>
__device__ __forceinline__ void gemm3(
    const u16* __restrict__ Ahi, const u16* __restrict__ Alo,
    const u16* __restrict__ Bhi, const u16* __restrict__ Blo,
    const int K, const int lda, const int ldb, const int ldc,
    float* __restrict__ C, u16* __restrict__ Chi, u16* __restrict__ Clo,
    const float* __restrict__ bias, const int m0, const int n0)
{
    __shared__ u16 sm[4 * 128 * PAD];

    const int tid  = threadIdx.x;
    const int lane = tid & 31, warp = tid >> 5;
    const int wm = warp >> 1, wn = warp & 1;
    const int qr = lane >> 2;           // fragment row within 8
    const int qc = (lane & 3) * 2;      // fragment k pair

    // gmem -> smem: each thread moves one uint4 (8 u16) x2 rows per matrix
    const int lrow = tid >> 2;          // 0..63
    const int lcol = (tid & 3) * 8;     // u16 elems

    const u16* gAh = Ahi + (size_t)(m0 + lrow) * lda + lcol;
    const u16* gAl = Alo + (size_t)(m0 + lrow) * lda + lcol;
    const u16* gBh = Bhi + (size_t)(n0 + lrow) * ldb + lcol;
    const u16* gBl = Blo + (size_t)(n0 + lrow) * ldb + lcol;
    const size_t skA = (size_t)64 * lda, skB = (size_t)64 * ldb;

    const int MOFF = 128 * PAD * 2;     // bytes per matrix buffer
    const int HOFF = 64 * PAD * 2;
    char* swp = (char*)sm + ((size_t)lrow * PAD + lcol) * 2;

    const uint32_t sbase = (uint32_t)__cvta_generic_to_shared(sm);
    // A x4: lanes 0-15 rows (lane&15), lanes 16-31 same rows at k+8.
    // -> r0=(qr,qc) r1=(qr+8,qc) r2=(qr,qc+8) r3=(qr+8,qc+8)
    const uint32_t aAddr = sbase + ((wm * 32 + (lane & 15)) * PAD + (lane >> 4) * 8) * 2;
    // B x4: lanes 0-7 n-rows 0-7 @k0; 8-15 n-rows 8-15 @k0; 16-23 rows 0-7 @k+8;
    // 24-31 rows 8-15 @k+8 -> r0=b0(tile even) r1=b0(tile odd) r2=b1(even) r3=b1(odd)
    const uint32_t bAddr = sbase + 2 * MOFF
        + ((wn * 64 + ((lane >> 3) & 1) * 8 + (lane & 7)) * PAD) * 2 + (lane >> 4) * 16;

    float c[2][8][4];
#pragma unroll
    for (int i = 0; i < 2; ++i)
#pragma unroll
        for (int j = 0; j < 8; ++j)
#pragma unroll
            for (int q = 0; q < 4; ++q) c[i][j][q] = 0.f;

    for (int k0 = 0; k0 < K; k0 += 32) {
        const uint4 vah0 = *(const uint4*)(gAh + k0);
        const uint4 vah1 = *(const uint4*)(gAh + k0 + skA);
        const uint4 val0 = *(const uint4*)(gAl + k0);
        const uint4 val1 = *(const uint4*)(gAl + k0 + skA);
        const uint4 vbh0 = *(const uint4*)(gBh + k0);
        const uint4 vbh1 = *(const uint4*)(gBh + k0 + skB);
        const uint4 vbl0 = *(const uint4*)(gBl + k0);
        const uint4 vbl1 = *(const uint4*)(gBl + k0 + skB);
        __syncthreads();                      // previous iter's compute done
        *(uint4*)(swp)                    = vah0;
        *(uint4*)(swp + HOFF)             = vah1;
        *(uint4*)(swp + MOFF)             = val0;
        *(uint4*)(swp + MOFF + HOFF)      = val1;
        *(uint4*)(swp + 2 * MOFF)         = vbh0;
        *(uint4*)(swp + 2 * MOFF + HOFF)  = vbh1;
        *(uint4*)(swp + 3 * MOFF)         = vbl0;
        *(uint4*)(swp + 3 * MOFF + HOFF)  = vbl1;
        __syncthreads();                      // tiles visible

#pragma unroll
        for (int ks = 0; ks < 2; ++ks) {
            const uint32_t ko = ks * 32;      // 16 u16 = 32 bytes along k

            uint32_t ah[2][4], al[2][4];
            ldsm4(ah[0], aAddr + ko);
            ldsm4(ah[1], aAddr + 16 * PAD * 2 + ko);
            ldsm4(al[0], aAddr + MOFF + ko);
            ldsm4(al[1], aAddr + MOFF + 16 * PAD * 2 + ko);

            uint32_t bh[8][2], bl[8][2];
#pragma unroll
            for (int tp = 0; tp < 4; ++tp) {
                uint32_t r[4];
                ldsm4(r, bAddr + tp * 16 * PAD * 2 + ko);
                bh[2 * tp][0] = r[0]; bh[2 * tp][1] = r[2];
                bh[2 * tp + 1][0] = r[1]; bh[2 * tp + 1][1] = r[3];
            }
#pragma unroll
            for (int tp = 0; tp < 4; ++tp) {
                uint32_t r[4];
                ldsm4(r, bAddr + MOFF + tp * 16 * PAD * 2 + ko);
                bl[2 * tp][0] = r[0]; bl[2 * tp][1] = r[2];
                bl[2 * tp + 1][0] = r[1]; bl[2 * tp + 1][1] = r[3];
            }
            // P1: Ahi*Bhi   P2: Ahi*Blo   P3: Alo*Bhi
#pragma unroll
            for (int tm = 0; tm < 2; ++tm)
#pragma unroll
                for (int tn = 0; tn < 8; ++tn) mma16(c[tm][tn], ah[tm], bh[tn]);
#pragma unroll
            for (int tm = 0; tm < 2; ++tm)
#pragma unroll
                for (int tn = 0; tn < 8; ++tn) mma16(c[tm][tn], ah[tm], bl[tn]);
#pragma unroll
            for (int tm = 0; tm < 2; ++tm)
#pragma unroll
                for (int tn = 0; tn < 8; ++tn) mma16(c[tm][tn], al[tm], bh[tn]);
        }
    }

    // epilogue (c fragment: c0,c1 = row qr cols qc..+1; c2,c3 = row qr+8)
    const int r0 = qr, cc = qc;
#pragma unroll
    for (int tm = 0; tm < 2; ++tm)
#pragma unroll
        for (int tn = 0; tn < 8; ++tn) {
            const int row = m0 + wm * 32 + tm * 16 + r0;
            const int col = n0 + wn * 64 + tn * 8 + cc;
#pragma unroll
            for (int hr = 0; hr < 2; ++hr) {
                const int rr = row + hr * 8;
                float v0 = c[tm][tn][hr * 2 + 0];
                float v1 = c[tm][tn][hr * 2 + 1];
                if (BIAS) { v0 += bias[col]; v1 += bias[col + 1]; }
                if (SPLIT_OUT) {
                    const u16 h0 = f2b(v0), h1 = f2b(v1);
                    const u16 l0 = f2b(v0 - b2f(h0)), l1 = f2b(v1 - b2f(h1));
                    *(uint32_t*)(Chi + (size_t)rr * ldc + col) =
                        ((uint32_t)h1 << 16) | (uint32_t)h0;
                    *(uint32_t*)(Clo + (size_t)rr * ldc + col) =
                        ((uint32_t)l1 << 16) | (uint32_t)l0;
                } else {
                    float2 v; v.x = v0; v.y = v1;
                    *(float2*)(C + (size_t)rr * ldc + col) = v;
                }
            }
        }
}

// ---------------- GEMM entry kernels (globals referenced in DEVICE code only) ----
__global__ __launch_bounds__(256) void k_qproj_t() {
    gemm3<true, false>(g_xhi, g_xlo, g_wqhi, g_wqlo,
                       DIM, DIM, DIM, 2 * DIM,
                       (float*)0, g_qhi, g_qlo, (const float*)0,
                       blockIdx.y * 128, blockIdx.x * 128);
}

__global__ __launch_bounds__(256) void k_dots_t() {
    const int z = blockIdx.z;
    const int b = z >> 4, h = (z >> 1) & 7, p = z & 1;
    const size_t aoff = (size_t)b * T_SEQ * (2 * DIM) + p * DIM + h * DHEAD;
    const size_t boff = (size_t)((h << 1) | p) * NKEYS * DHEAD;
    gemm3<false, false>(g_qhi + aoff, g_qlo + aoff, g_khi + boff, g_klo + boff,
                        DHEAD, 2 * DIM, DHEAD, NKEYS,
                        g_dots + (size_t)z * T_SEQ * NKEYS, (u16*)0, (u16*)0,
                        (const float*)0,
                        blockIdx.y * 128, blockIdx.x * 128);
}

__global__ __launch_bounds__(256) void k_outproj_t(const float* __restrict__ bo,
                                                   float* __restrict__ out) {
    gemm3<false, true>(g_ahi, g_alo, g_wohi, g_wolo,
                       DIM, DIM, DIM, DIM,
                       out, (u16*)0, (u16*)0, bo,
                       blockIdx.y * 128, blockIdx.x * 128);
}

// ---------------- split conversions ----------------
// Destination __device__ globals must be named in DEVICE code, never passed as
// host-side kernel args (host sees shadow addresses; ATS writes host memory).
__device__ __forceinline__ void split_one(const float* __restrict__ s,
                                          u16* __restrict__ hi,
                                          u16* __restrict__ lo, int n) {
    const int i = blockIdx.x * 256 + threadIdx.x;
    if (i < n) {
        const float v = s[i];
        const u16 a = f2b(v);
        hi[i] = a;
        lo[i] = f2b(v - b2f(a));
    }
}
__global__ void k_split_x (const float* __restrict__ s) { split_one(s, g_xhi,  g_xlo,  NBATCH * T_SEQ * DIM); }
__global__ void k_split_wq(const float* __restrict__ s) { split_one(s, g_wqhi, g_wqlo, 2 * DIM * DIM); }
__global__ void k_split_wo(const float* __restrict__ s) { split_one(s, g_wohi, g_wolo, DIM * DIM); }

// keys[h][n][p][d] -> g_khi/klo[(h*2+p)][n][d]
__global__ void k_split_keys(const float* __restrict__ keys) {
    const int i = blockIdx.x * 256 + threadIdx.x;
    if (i < 16 * NKEYS * DHEAD) {
        const int d = i & 127;
        const int n = (i >> 7) & 255;
        const int zk = i >> 15;
        const int h = zk >> 1, p = zk & 1;
        const float v = keys[(((size_t)(h * NKEYS + n) * 2 + p) << 7) + d];
        const u16 a = f2b(v);
        g_khi[i] = a;
        g_klo[i] = f2b(v - b2f(a));
    }
}

// ---------------- stage-1 top-32 of 256 per row (one warp/row) ----------------
__global__ __launch_bounds__(256) void k_topk1() {
    const int warp = threadIdx.x >> 5;
    const int lane = threadIdx.x & 31;
    const size_t row = (size_t)blockIdx.x * 8 + warp;
    const float* d = g_dots + row * NKEYS;
    const float NEGINF = __int_as_float(0xff800000);

    float v[8];
#pragma unroll
    for (int j = 0; j < 8; ++j) v[j] = d[j * 32 + lane];

    float* outs = g_s1s + row * TOPK;
    int*   outi = g_s1i + row * TOPK;

    for (int it = 0; it < TOPK; ++it) {
        float bv = NEGINF;
        int   bn = 1 << 30;
#pragma unroll
        for (int j = 0; j < 8; ++j) {
            const int n = j * 32 + lane;
            if (v[j] > bv) { bv = v[j]; bn = n; }
        }
#pragma unroll
        for (int off = 16; off > 0; off >>= 1) {
            const float ov = __shfl_xor_sync(0xffffffffu, bv, off);
            const int   on = __shfl_xor_sync(0xffffffffu, bn, off);
            if (ov > bv || (ov == bv && on < bn)) { bv = ov; bn = on; }
        }
        if (lane == 0) { outs[it] = bv; outi[it] = bn; }
        const int wl = bn & 31, wj = bn >> 5;
#pragma unroll
        for (int j = 0; j < 8; ++j)
            if (lane == wl && j == wj) v[j] = NEGINF;
    }
}

// ---------------- stage-2: combine + softmax + gather (writes split attn) ----------------
__global__ __launch_bounds__(128) void k_stage2(const float* __restrict__ values) {
    const int tp = blockIdx.x;
    const int b  = blockIdx.y, h = blockIdx.z;
    const int i  = tp >> 1, p = tp & 1;
    const int z  = ((b * HEADS + h) << 1) + p;
    const size_t baseA = ((size_t)z * T_SEQ + i) * TOPK;
    const size_t baseB = ((size_t)z * T_SEQ + (T_SEQ / 2) + i) * TOPK;

    __shared__ float sA[32], sB[32], csum[128], topS[32], w[32];
    __shared__ int   iA[32], iB[32], topI[32];

    const int tid = threadIdx.x;
    const float NEGINF = __int_as_float(0xff800000);

    if (tid < 32)      { sA[tid] = g_s1s[baseA + tid]; iA[tid] = g_s1i[baseA + tid]; }
    else if (tid < 64) { const int r = tid - 32; sB[r] = g_s1s[baseB + r]; iB[r] = g_s1i[baseB + r]; }
    csum[tid] = NEGINF;
    __syncthreads();

    // Pareto candidate set {(a,c): (a+1)*(c+1) <= 32}, 119 members.
    int a = 0, c = 0;
    float myv = NEGINF;
    if (tid < 119) {
        int base = 0;
        while (base + 32 / (a + 1) <= tid) { base += 32 / (a + 1); ++a; }
        c = tid - base;
        myv = sA[a] + sB[c];
        csum[tid] = myv;
    }
    __syncthreads();

    if (tid < 119) {
        int rank = 0;
        for (int j = 0; j < 119; ++j) {
            const float vj = csum[j];
            rank += (vj > myv) || (vj == myv && j < tid);
        }
        if (rank < 32) {
            topS[rank] = myv;
            topI[rank] = iA[a] * NKEYS + iB[c];
        }
    }
    __syncthreads();

    if (tid < 32) {
        const float e = expf(topS[tid] - topS[0]);
        float s = e;
#pragma unroll
        for (int off = 16; off > 0; off >>= 1) s += __shfl_xor_sync(0xffffffffu, s, off);
        w[tid] = e / s;
    }
    __syncthreads();

    const float* V = values + (size_t)h * (NKEYS * NKEYS) * DHEAD;
    float acc = 0.f;
#pragma unroll
    for (int j = 0; j < 32; ++j)
        acc = fmaf(w[j], V[(size_t)topI[j] * DHEAD + tid], acc);

    const size_t oidx = ((size_t)(b * T_SEQ + tp)) * DIM + h * DHEAD + tid;
    const u16 hv = f2b(acc);
    g_ahi[oidx] = hv;
    g_alo[oidx] = f2b(acc - b2f(hv));
}

// ---------------- launch ----------------
extern "C" void kernel_launch(void* const* d_in, const int* in_sizes, int n_in,
                              void* d_out, int out_size)
{
    const float* x      = (const float*)d_in[0];
    const float* Wq     = (const float*)d_in[1];
    const float* keys   = (const float*)d_in[2];
    const float* values = (const float*)d_in[3];
    const float* Wo     = (const float*)d_in[4];
    const float* bo     = (const float*)d_in[5];
    float* out = (float*)d_out;

    const int nX  = NBATCH * T_SEQ * DIM;
    const int nWq = 2 * DIM * DIM;
    const int nWo = DIM * DIM;

    k_split_x <<<(nX  + 255) / 256, 256>>>(x);
    k_split_wq<<<(nWq + 255) / 256, 256>>>(Wq);
    k_split_wo<<<(nWo + 255) / 256, 256>>>(Wo);
    k_split_keys<<<(16 * NKEYS * DHEAD) / 256, 256>>>(keys);

    k_qproj_t<<<dim3(16, 32), 256>>>();
    k_dots_t <<<dim3(2, 16, 32), 256>>>();
    k_topk1  <<<(32 * T_SEQ) / 8, 256>>>();
    k_stage2 <<<dim3(T_SEQ, NBATCH, HEADS), 128>>>(values);
    k_outproj_t<<<dim3(8, 32), 256>>>(bo, out);
}

// round 13
// speedup vs baseline: 1.0201x; 1.0201x over previous
#include <cuda_runtime.h>
#include <stdint.h>
#include <math.h>

#define T_SEQ  2048
#define NBATCH 2
#define DIM    1024
#define HEADS  8
#define NKEYS  256
#define TOPK   32
#define DHEAD  128

// bf16 stored as raw uint16 — no cuda_bf16.h anywhere.
typedef unsigned short u16;

__device__ __forceinline__ u16 f2b(float v) {
    const uint32_t u = __float_as_uint(v);
    return (u16)((u + 0x7fffu + ((u >> 16) & 1u)) >> 16);   // round-nearest-even
}
__device__ __forceinline__ float b2f(u16 h) {
    return __uint_as_float(((uint32_t)h) << 16);
}

// ---------------- scratch (static device globals; no allocation) ----------------
__device__ __align__(16) u16 g_xhi [(size_t)NBATCH * T_SEQ * DIM];
__device__ __align__(16) u16 g_xlo [(size_t)NBATCH * T_SEQ * DIM];
__device__ __align__(16) u16 g_wqhi[(size_t)2 * DIM * DIM];
__device__ __align__(16) u16 g_wqlo[(size_t)2 * DIM * DIM];
__device__ __align__(16) u16 g_wohi[(size_t)DIM * DIM];
__device__ __align__(16) u16 g_wolo[(size_t)DIM * DIM];
__device__ __align__(16) u16 g_khi [(size_t)16 * NKEYS * DHEAD];   // [zk=h*2+p][n][d]
__device__ __align__(16) u16 g_klo [(size_t)16 * NKEYS * DHEAD];
__device__ __align__(16) u16 g_qhi [(size_t)NBATCH * T_SEQ * 2 * DIM];
__device__ __align__(16) u16 g_qlo [(size_t)NBATCH * T_SEQ * 2 * DIM];
__device__ __align__(16) u16 g_ahi [(size_t)NBATCH * T_SEQ * DIM];  // attn pre-Wo
__device__ __align__(16) u16 g_alo [(size_t)NBATCH * T_SEQ * DIM];
__device__ float g_dots[(size_t)32 * T_SEQ * NKEYS];   // (z = b*16+h*2+p, t, n)
__device__ float g_s1s [(size_t)32 * T_SEQ * TOPK];
__device__ int   g_s1i [(size_t)32 * T_SEQ * TOPK];

// ---------------- tensor-core primitive ----------------
__device__ __forceinline__ void mma16(float* c, const uint32_t* a, const uint32_t* b) {
    asm volatile("mma.sync.aligned.m16n8k16.row.col.f32.bf16.bf16.f32 "
        "{%0,%1,%2,%3},{%4,%5,%6,%7},{%8,%9},{%0,%1,%2,%3};"
        : "+f"(c[0]), "+f"(c[1]), "+f"(c[2]), "+f"(c[3])
        : "r"(a[0]), "r"(a[1]), "r"(a[2]), "r"(a[3]), "r"(b[0]), "r"(b[1]));
}

// ---------------- bf16x3 split GEMM: C = A(MxK) * B(NxK)^T ----------------
// Block tile 128x128, BK=32, 256 threads (8 warps as 4m x 2n, warp tile 32x64).
// Direct per-thread LDS fragment feed (mma.m16n8k16 fragment spec).
// 2-stage double-buffered smem pipeline, ONE __syncthreads per K-iteration:
//   [ LDG(next)->regs ; compute(cur) ; STS(next) ; sync ]
// PAD=40 u16/row: 80B stride cycles 8 distinct bank phases -> conflict-free.
#define PAD 40
#define SMSTAGE (4 * 128 * PAD)              // u16 elems per stage
#define GEMM_SMEM_BYTES (2 * SMSTAGE * 2)    // 81920 bytes

template<bool SPLIT_OUT, bool BIAS>
__device__ __forceinline__ void gemm3(
    const u16* __restrict__ Ahi, const u16* __restrict__ Alo,
    const u16* __restrict__ Bhi, const u16* __restrict__ Blo,
    const int K, const int lda, const int ldb, const int ldc,
    float* __restrict__ C, u16* __restrict__ Chi, u16* __restrict__ Clo,
    const float* __restrict__ bias, const int m0, const int n0)
{
    extern __shared__ u16 smdyn[];

    const int tid  = threadIdx.x;
    const int lane = tid & 31, warp = tid >> 5;
    const int wm = warp >> 1, wn = warp & 1;
    const int qr = lane >> 2;           // 0..7   fragment row
    const int qc = (lane & 3) * 2;      // 0,2,4,6 fragment k pair

    // gmem -> smem: each thread moves one uint4 (8 u16) x2 rows per matrix
    const int lrow = tid >> 2;          // 0..63
    const int lcol = (tid & 3) * 8;     // u16 elems

    const u16* gAh = Ahi + (size_t)(m0 + lrow) * lda + lcol;
    const u16* gAl = Alo + (size_t)(m0 + lrow) * lda + lcol;
    const u16* gBh = Bhi + (size_t)(n0 + lrow) * ldb + lcol;
    const u16* gBl = Blo + (size_t)(n0 + lrow) * ldb + lcol;
    const size_t skA = (size_t)64 * lda, skB = (size_t)64 * ldb;

    const int MOFF = 128 * PAD * 2;     // bytes per matrix buffer within a stage
    const int HOFF = 64 * PAD * 2;
    const int swoff = (lrow * PAD + lcol) * 2;

#define FRAG(base, boff, r, k) \
    (*(const uint32_t*)((base) + (boff) + (((r) * PAD + (k)) * 2)))

    float c[2][8][4];
#pragma unroll
    for (int i = 0; i < 2; ++i)
#pragma unroll
        for (int j = 0; j < 8; ++j)
#pragma unroll
            for (int q = 0; q < 4; ++q) c[i][j][q] = 0.f;

    const int NIT = K >> 5;             // K / 32

    // ---- prologue: fill stage 0 ----
    {
        const uint4 vah0 = *(const uint4*)(gAh);
        const uint4 vah1 = *(const uint4*)(gAh + skA);
        const uint4 val0 = *(const uint4*)(gAl);
        const uint4 val1 = *(const uint4*)(gAl + skA);
        const uint4 vbh0 = *(const uint4*)(gBh);
        const uint4 vbh1 = *(const uint4*)(gBh + skB);
        const uint4 vbl0 = *(const uint4*)(gBl);
        const uint4 vbl1 = *(const uint4*)(gBl + skB);
        char* swp = (char*)smdyn + swoff;
        *(uint4*)(swp)                    = vah0;
        *(uint4*)(swp + HOFF)             = vah1;
        *(uint4*)(swp + MOFF)             = val0;
        *(uint4*)(swp + MOFF + HOFF)      = val1;
        *(uint4*)(swp + 2 * MOFF)         = vbh0;
        *(uint4*)(swp + 2 * MOFF + HOFF)  = vbh1;
        *(uint4*)(swp + 3 * MOFF)         = vbl0;
        *(uint4*)(swp + 3 * MOFF + HOFF)  = vbl1;
    }
    __syncthreads();

    for (int it = 0; it < NIT; ++it) {
        const int cur = it & 1;
        const bool more = (it + 1) < NIT;

        // ---- issue next tile's global loads early (latency hides under MMAs) ----
        uint4 vah0, vah1, val0, val1, vbh0, vbh1, vbl0, vbl1;
        if (more) {
            const int kn = (it + 1) << 5;
            vah0 = *(const uint4*)(gAh + kn);
            vah1 = *(const uint4*)(gAh + kn + skA);
            val0 = *(const uint4*)(gAl + kn);
            val1 = *(const uint4*)(gAl + kn + skA);
            vbh0 = *(const uint4*)(gBh + kn);
            vbh1 = *(const uint4*)(gBh + kn + skB);
            vbl0 = *(const uint4*)(gBl + kn);
            vbl1 = *(const uint4*)(gBl + kn + skB);
        }

        // ---- compute on current stage ----
        const char* smc = (const char*)(smdyn + cur * SMSTAGE);
#pragma unroll
        for (int ks = 0; ks < 2; ++ks) {
            const int kk = ks * 16 + qc;

            uint32_t ah[2][4], al[2][4], bh[8][2], bl[8][2];
#pragma unroll
            for (int tm = 0; tm < 2; ++tm) {
                const int r = wm * 32 + tm * 16 + qr;
                ah[tm][0] = FRAG(smc, 0,    r,     kk);
                ah[tm][1] = FRAG(smc, 0,    r + 8, kk);
                ah[tm][2] = FRAG(smc, 0,    r,     kk + 8);
                ah[tm][3] = FRAG(smc, 0,    r + 8, kk + 8);
                al[tm][0] = FRAG(smc, MOFF, r,     kk);
                al[tm][1] = FRAG(smc, MOFF, r + 8, kk);
                al[tm][2] = FRAG(smc, MOFF, r,     kk + 8);
                al[tm][3] = FRAG(smc, MOFF, r + 8, kk + 8);
            }
#pragma unroll
            for (int tn = 0; tn < 8; ++tn) {
                const int r = wn * 64 + tn * 8 + qr;
                bh[tn][0] = FRAG(smc, 2 * MOFF, r, kk);
                bh[tn][1] = FRAG(smc, 2 * MOFF, r, kk + 8);
                bl[tn][0] = FRAG(smc, 3 * MOFF, r, kk);
                bl[tn][1] = FRAG(smc, 3 * MOFF, r, kk + 8);
            }
            // P1: Ahi*Bhi   P2: Ahi*Blo   P3: Alo*Bhi
#pragma unroll
            for (int tm = 0; tm < 2; ++tm)
#pragma unroll
                for (int tn = 0; tn < 8; ++tn) mma16(c[tm][tn], ah[tm], bh[tn]);
#pragma unroll
            for (int tm = 0; tm < 2; ++tm)
#pragma unroll
                for (int tn = 0; tn < 8; ++tn) mma16(c[tm][tn], ah[tm], bl[tn]);
#pragma unroll
            for (int tm = 0; tm < 2; ++tm)
#pragma unroll
                for (int tn = 0; tn < 8; ++tn) mma16(c[tm][tn], al[tm], bh[tn]);
        }

        // ---- stage the next tile (disjoint buffer from 'cur') ----
        if (more) {
            char* swp = (char*)(smdyn + (cur ^ 1) * SMSTAGE) + swoff;
            *(uint4*)(swp)                    = vah0;
            *(uint4*)(swp + HOFF)             = vah1;
            *(uint4*)(swp + MOFF)             = val0;
            *(uint4*)(swp + MOFF + HOFF)      = val1;
            *(uint4*)(swp + 2 * MOFF)         = vbh0;
            *(uint4*)(swp + 2 * MOFF + HOFF)  = vbh1;
            *(uint4*)(swp + 3 * MOFF)         = vbl0;
            *(uint4*)(swp + 3 * MOFF + HOFF)  = vbl1;
        }
        __syncthreads();
    }
#undef FRAG

    // epilogue (c fragment: c0,c1 = row qr cols qc..+1; c2,c3 = row qr+8)
    const int r0 = qr, cc = qc;
#pragma unroll
    for (int tm = 0; tm < 2; ++tm)
#pragma unroll
        for (int tn = 0; tn < 8; ++tn) {
            const int row = m0 + wm * 32 + tm * 16 + r0;
            const int col = n0 + wn * 64 + tn * 8 + cc;
#pragma unroll
            for (int hr = 0; hr < 2; ++hr) {
                const int rr = row + hr * 8;
                float v0 = c[tm][tn][hr * 2 + 0];
                float v1 = c[tm][tn][hr * 2 + 1];
                if (BIAS) { v0 += bias[col]; v1 += bias[col + 1]; }
                if (SPLIT_OUT) {
                    const u16 h0 = f2b(v0), h1 = f2b(v1);
                    const u16 l0 = f2b(v0 - b2f(h0)), l1 = f2b(v1 - b2f(h1));
                    *(uint32_t*)(Chi + (size_t)rr * ldc + col) =
                        ((uint32_t)h1 << 16) | (uint32_t)h0;
                    *(uint32_t*)(Clo + (size_t)rr * ldc + col) =
                        ((uint32_t)l1 << 16) | (uint32_t)l0;
                } else {
                    float2 v; v.x = v0; v.y = v1;
                    *(float2*)(C + (size_t)rr * ldc + col) = v;
                }
            }
        }
}

// ---------------- GEMM entry kernels (globals referenced in DEVICE code only) ----
__global__ __launch_bounds__(256) void k_qproj_t() {
    gemm3<true, false>(g_xhi, g_xlo, g_wqhi, g_wqlo,
                       DIM, DIM, DIM, 2 * DIM,
                       (float*)0, g_qhi, g_qlo, (const float*)0,
                       blockIdx.y * 128, blockIdx.x * 128);
}

__global__ __launch_bounds__(256) void k_dots_t() {
    const int z = blockIdx.z;
    const int b = z >> 4, h = (z >> 1) & 7, p = z & 1;
    const size_t aoff = (size_t)b * T_SEQ * (2 * DIM) + p * DIM + h * DHEAD;
    const size_t boff = (size_t)((h << 1) | p) * NKEYS * DHEAD;
    gemm3<false, false>(g_qhi + aoff, g_qlo + aoff, g_khi + boff, g_klo + boff,
                        DHEAD, 2 * DIM, DHEAD, NKEYS,
                        g_dots + (size_t)z * T_SEQ * NKEYS, (u16*)0, (u16*)0,
                        (const float*)0,
                        blockIdx.y * 128, blockIdx.x * 128);
}

__global__ __launch_bounds__(256) void k_outproj_t(const float* __restrict__ bo,
                                                   float* __restrict__ out) {
    gemm3<false, true>(g_ahi, g_alo, g_wohi, g_wolo,
                       DIM, DIM, DIM, DIM,
                       out, (u16*)0, (u16*)0, bo,
                       blockIdx.y * 128, blockIdx.x * 128);
}

// ---------------- split conversions ----------------
// Destination __device__ globals must be named in DEVICE code, never passed as
// host-side kernel args (host sees shadow addresses; ATS writes host memory).
__device__ __forceinline__ void split_one(const float* __restrict__ s,
                                          u16* __restrict__ hi,
                                          u16* __restrict__ lo, int n) {
    const int i = blockIdx.x * 256 + threadIdx.x;
    if (i < n) {
        const float v = s[i];
        const u16 a = f2b(v);
        hi[i] = a;
        lo[i] = f2b(v - b2f(a));
    }
}
__global__ void k_split_x (const float* __restrict__ s) { split_one(s, g_xhi,  g_xlo,  NBATCH * T_SEQ * DIM); }
__global__ void k_split_wq(const float* __restrict__ s) { split_one(s, g_wqhi, g_wqlo, 2 * DIM * DIM); }
__global__ void k_split_wo(const float* __restrict__ s) { split_one(s, g_wohi, g_wolo, DIM * DIM); }

// keys[h][n][p][d] -> g_khi/klo[(h*2+p)][n][d]
__global__ void k_split_keys(const float* __restrict__ keys) {
    const int i = blockIdx.x * 256 + threadIdx.x;
    if (i < 16 * NKEYS * DHEAD) {
        const int d = i & 127;
        const int n = (i >> 7) & 255;
        const int zk = i >> 15;
        const int h = zk >> 1, p = zk & 1;
        const float v = keys[(((size_t)(h * NKEYS + n) * 2 + p) << 7) + d];
        const u16 a = f2b(v);
        g_khi[i] = a;
        g_klo[i] = f2b(v - b2f(a));
    }
}

// ---------------- stage-1 top-32 of 256 per row (one warp/row) ----------------
__global__ __launch_bounds__(256) void k_topk1() {
    const int warp = threadIdx.x >> 5;
    const int lane = threadIdx.x & 31;
    const size_t row = (size_t)blockIdx.x * 8 + warp;
    const float* d = g_dots + row * NKEYS;
    const float NEGINF = __int_as_float(0xff800000);

    float v[8];
#pragma unroll
    for (int j = 0; j < 8; ++j) v[j] = d[j * 32 + lane];

    float* outs = g_s1s + row * TOPK;
    int*   outi = g_s1i + row * TOPK;

    for (int it = 0; it < TOPK; ++it) {
        float bv = NEGINF;
        int   bn = 1 << 30;
#pragma unroll
        for (int j = 0; j < 8; ++j) {
            const int n = j * 32 + lane;
            if (v[j] > bv) { bv = v[j]; bn = n; }
        }
#pragma unroll
        for (int off = 16; off > 0; off >>= 1) {
            const float ov = __shfl_xor_sync(0xffffffffu, bv, off);
            const int   on = __shfl_xor_sync(0xffffffffu, bn, off);
            if (ov > bv || (ov == bv && on < bn)) { bv = ov; bn = on; }
        }
        if (lane == 0) { outs[it] = bv; outi[it] = bn; }
        const int wl = bn & 31, wj = bn >> 5;
#pragma unroll
        for (int j = 0; j < 8; ++j)
            if (lane == wl && j == wj) v[j] = NEGINF;
    }
}

// ---------------- stage-2: combine + softmax + gather (writes split attn) ----------------
__global__ __launch_bounds__(128) void k_stage2(const float* __restrict__ values) {
    const int tp = blockIdx.x;
    const int b  = blockIdx.y, h = blockIdx.z;
    const int i  = tp >> 1, p = tp & 1;
    const int z  = ((b * HEADS + h) << 1) + p;
    const size_t baseA = ((size_t)z * T_SEQ + i) * TOPK;
    const size_t baseB = ((size_t)z * T_SEQ + (T_SEQ / 2) + i) * TOPK;

    __shared__ float sA[32], sB[32], csum[128], topS[32], w[32];
    __shared__ int   iA[32], iB[32], topI[32];

    const int tid = threadIdx.x;
    const float NEGINF = __int_as_float(0xff800000);

    if (tid < 32)      { sA[tid] = g_s1s[baseA + tid]; iA[tid] = g_s1i[baseA + tid]; }
    else if (tid < 64) { const int r = tid - 32; sB[r] = g_s1s[baseB + r]; iB[r] = g_s1i[baseB + r]; }
    csum[tid] = NEGINF;
    __syncthreads();

    // Pareto candidate set {(a,c): (a+1)*(c+1) <= 32}, 119 members.
    int a = 0, c = 0;
    float myv = NEGINF;
    if (tid < 119) {
        int base = 0;
        while (base + 32 / (a + 1) <= tid) { base += 32 / (a + 1); ++a; }
        c = tid - base;
        myv = sA[a] + sB[c];
        csum[tid] = myv;
    }
    __syncthreads();

    if (tid < 119) {
        int rank = 0;
        for (int j = 0; j < 119; ++j) {
            const float vj = csum[j];
            rank += (vj > myv) || (vj == myv && j < tid);
        }
        if (rank < 32) {
            topS[rank] = myv;
            topI[rank] = iA[a] * NKEYS + iB[c];
        }
    }
    __syncthreads();

    if (tid < 32) {
        const float e = expf(topS[tid] - topS[0]);
        float s = e;
#pragma unroll
        for (int off = 16; off > 0; off >>= 1) s += __shfl_xor_sync(0xffffffffu, s, off);
        w[tid] = e / s;
    }
    __syncthreads();

    const float* V = values + (size_t)h * (NKEYS * NKEYS) * DHEAD;
    float acc = 0.f;
#pragma unroll
    for (int j = 0; j < 32; ++j)
        acc = fmaf(w[j], V[(size_t)topI[j] * DHEAD + tid], acc);

    const size_t oidx = ((size_t)(b * T_SEQ + tp)) * DIM + h * DHEAD + tid;
    const u16 hv = f2b(acc);
    g_ahi[oidx] = hv;
    g_alo[oidx] = f2b(acc - b2f(hv));
}

// ---------------- launch ----------------
extern "C" void kernel_launch(void* const* d_in, const int* in_sizes, int n_in,
                              void* d_out, int out_size)
{
    const float* x      = (const float*)d_in[0];
    const float* Wq     = (const float*)d_in[1];
    const float* keys   = (const float*)d_in[2];
    const float* values = (const float*)d_in[3];
    const float* Wo     = (const float*)d_in[4];
    const float* bo     = (const float*)d_in[5];
    float* out = (float*)d_out;

    const int nX  = NBATCH * T_SEQ * DIM;
    const int nWq = 2 * DIM * DIM;
    const int nWo = DIM * DIM;

    // dynamic smem opt-in (80 KB > 48 KB static limit); host-side, idempotent
    cudaFuncSetAttribute(k_qproj_t,   cudaFuncAttributeMaxDynamicSharedMemorySize, GEMM_SMEM_BYTES);
    cudaFuncSetAttribute(k_dots_t,    cudaFuncAttributeMaxDynamicSharedMemorySize, GEMM_SMEM_BYTES);
    cudaFuncSetAttribute(k_outproj_t, cudaFuncAttributeMaxDynamicSharedMemorySize, GEMM_SMEM_BYTES);

    k_split_x <<<(nX  + 255) / 256, 256>>>(x);
    k_split_wq<<<(nWq + 255) / 256, 256>>>(Wq);
    k_split_wo<<<(nWo + 255) / 256, 256>>>(Wo);
    k_split_keys<<<(16 * NKEYS * DHEAD) / 256, 256>>>(keys);

    k_qproj_t<<<dim3(16, 32), 256, GEMM_SMEM_BYTES>>>();
    k_dots_t <<<dim3(2, 16, 32), 256, GEMM_SMEM_BYTES>>>();
    k_topk1  <<<(32 * T_SEQ) / 8, 256>>>();
    k_stage2 <<<dim3(T_SEQ, NBATCH, HEADS), 128>>>(values);
    k_outproj_t<<<dim3(8, 32), 256, GEMM_SMEM_BYTES>>>(bo, out);
}

// round 15
// speedup vs baseline: 1.1999x; 1.1763x over previous
#include <cuda_runtime.h>
#include <stdint.h>
#include <math.h>

#define T_SEQ  2048
#define NBATCH 2
#define DIM    1024
#define HEADS  8
#define NKEYS  256
#define TOPK   32
#define DHEAD  128

// bf16 stored as raw uint16 — no cuda_bf16.h anywhere.
typedef unsigned short u16;

__device__ __forceinline__ u16 f2b(float v) {
    const uint32_t u = __float_as_uint(v);
    return (u16)((u + 0x7fffu + ((u >> 16) & 1u)) >> 16);   // round-nearest-even
}
__device__ __forceinline__ float b2f(u16 h) {
    return __uint_as_float(((uint32_t)h) << 16);
}

// ---------------- scratch (static device globals; no allocation) ----------------
__device__ __align__(16) u16 g_xhi [(size_t)NBATCH * T_SEQ * DIM];
__device__ __align__(16) u16 g_xlo [(size_t)NBATCH * T_SEQ * DIM];
__device__ __align__(16) u16 g_wqhi[(size_t)2 * DIM * DIM];
__device__ __align__(16) u16 g_wqlo[(size_t)2 * DIM * DIM];
__device__ __align__(16) u16 g_wohi[(size_t)DIM * DIM];
__device__ __align__(16) u16 g_wolo[(size_t)DIM * DIM];
__device__ __align__(16) u16 g_khi [(size_t)16 * NKEYS * DHEAD];   // [zk=h*2+p][n][d]
__device__ __align__(16) u16 g_klo [(size_t)16 * NKEYS * DHEAD];
__device__ __align__(16) u16 g_qhi [(size_t)NBATCH * T_SEQ * 2 * DIM];
__device__ __align__(16) u16 g_qlo [(size_t)NBATCH * T_SEQ * 2 * DIM];
__device__ __align__(16) u16 g_ahi [(size_t)NBATCH * T_SEQ * DIM];  // attn pre-Wo
__device__ __align__(16) u16 g_alo [(size_t)NBATCH * T_SEQ * DIM];
__device__ float g_dots[(size_t)32 * T_SEQ * NKEYS];   // (z = b*16+h*2+p, t, n)
__device__ float g_s1s [(size_t)32 * T_SEQ * TOPK];
__device__ int   g_s1i [(size_t)32 * T_SEQ * TOPK];

// Pareto candidate table for stage-2: (a<<8)|c for all (a,c) with
// (a+1)*(c+1) <= 32, in lexicographic (a,c) order (119 entries, padded to 128).
__device__ const u16 g_pareto[128] = {
    // a=0, c=0..31
    0x0000,0x0001,0x0002,0x0003,0x0004,0x0005,0x0006,0x0007,
    0x0008,0x0009,0x000A,0x000B,0x000C,0x000D,0x000E,0x000F,
    0x0010,0x0011,0x0012,0x0013,0x0014,0x0015,0x0016,0x0017,
    0x0018,0x0019,0x001A,0x001B,0x001C,0x001D,0x001E,0x001F,
    // a=1, c=0..15
    0x0100,0x0101,0x0102,0x0103,0x0104,0x0105,0x0106,0x0107,
    0x0108,0x0109,0x010A,0x010B,0x010C,0x010D,0x010E,0x010F,
    // a=2, c=0..9
    0x0200,0x0201,0x0202,0x0203,0x0204,0x0205,0x0206,0x0207,0x0208,0x0209,
    // a=3, c=0..7
    0x0300,0x0301,0x0302,0x0303,0x0304,0x0305,0x0306,0x0307,
    // a=4, c=0..5
    0x0400,0x0401,0x0402,0x0403,0x0404,0x0405,
    // a=5, c=0..4
    0x0500,0x0501,0x0502,0x0503,0x0504,
    // a=6, c=0..3
    0x0600,0x0601,0x0602,0x0603,
    // a=7, c=0..3
    0x0700,0x0701,0x0702,0x0703,
    // a=8, c=0..2
    0x0800,0x0801,0x0802,
    // a=9, c=0..2
    0x0900,0x0901,0x0902,
    // a=10..15, c=0..1
    0x0A00,0x0A01,0x0B00,0x0B01,0x0C00,0x0C01,
    0x0D00,0x0D01,0x0E00,0x0E01,0x0F00,0x0F01,
    // a=16..31, c=0
    0x1000,0x1100,0x1200,0x1300,0x1400,0x1500,0x1600,0x1700,
    0x1800,0x1900,0x1A00,0x1B00,0x1C00,0x1D00,0x1E00,0x1F00,
    // pad
    0xFFFF,0xFFFF,0xFFFF,0xFFFF,0xFFFF,0xFFFF,0xFFFF,0xFFFF,0xFFFF
};

// ---------------- tensor-core primitive ----------------
__device__ __forceinline__ void mma16(float* c, const uint32_t* a, const uint32_t* b) {
    asm volatile("mma.sync.aligned.m16n8k16.row.col.f32.bf16.bf16.f32 "
        "{%0,%1,%2,%3},{%4,%5,%6,%7},{%8,%9},{%0,%1,%2,%3};"
        : "+f"(c[0]), "+f"(c[1]), "+f"(c[2]), "+f"(c[3])
        : "r"(a[0]), "r"(a[1]), "r"(a[2]), "r"(a[3]), "r"(b[0]), "r"(b[1]));
}

// ---------------- bf16x3 split GEMM: C = A(MxK) * B(NxK)^T ----------------
// (exact round-7 best-measured version: static 40KB smem -> 2 CTAs/SM,
//  direct per-thread LDS fragment feed, simple single-buffer loop)
#define PAD 40

template<bool SPLIT_OUT, bool BIAS>
__device__ __forceinline__ void gemm3(
    const u16* __restrict__ Ahi, const u16* __restrict__ Alo,
    const u16* __restrict__ Bhi, const u16* __restrict__ Blo,
    const int K, const int lda, const int ldb, const int ldc,
    float* __restrict__ C, u16* __restrict__ Chi, u16* __restrict__ Clo,
    const float* __restrict__ bias, const int m0, const int n0)
{
    __shared__ u16 sm[4 * 128 * PAD];

    const int tid  = threadIdx.x;
    const int lane = tid & 31, warp = tid >> 5;
    const int wm = warp >> 1, wn = warp & 1;
    const int qr = lane >> 2;           // 0..7   fragment row
    const int qc = (lane & 3) * 2;      // 0,2,4,6 fragment k pair

    const int lrow = tid >> 2;          // 0..63
    const int lcol = (tid & 3) * 8;     // u16 elems

    const u16* gAh = Ahi + (size_t)(m0 + lrow) * lda + lcol;
    const u16* gAl = Alo + (size_t)(m0 + lrow) * lda + lcol;
    const u16* gBh = Bhi + (size_t)(n0 + lrow) * ldb + lcol;
    const u16* gBl = Blo + (size_t)(n0 + lrow) * ldb + lcol;
    const size_t skA = (size_t)64 * lda, skB = (size_t)64 * ldb;

    const int MOFF = 128 * PAD * 2;     // bytes per matrix buffer
    const int HOFF = 64 * PAD * 2;
    char* swp = (char*)sm + ((size_t)lrow * PAD + lcol) * 2;
    const char* smc = (const char*)sm;

#define AHI_F(r, k) (*(const uint32_t*)(smc            + (((r) * PAD + (k)) * 2)))
#define ALO_F(r, k) (*(const uint32_t*)(smc +     MOFF + (((r) * PAD + (k)) * 2)))
#define BHI_F(r, k) (*(const uint32_t*)(smc + 2 * MOFF + (((r) * PAD + (k)) * 2)))
#define BLO_F(r, k) (*(const uint32_t*)(smc + 3 * MOFF + (((r) * PAD + (k)) * 2)))

    float c[2][8][4];
#pragma unroll
    for (int i = 0; i < 2; ++i)
#pragma unroll
        for (int j = 0; j < 8; ++j)
#pragma unroll
            for (int q = 0; q < 4; ++q) c[i][j][q] = 0.f;

    for (int k0 = 0; k0 < K; k0 += 32) {
        const uint4 vah0 = *(const uint4*)(gAh + k0);
        const uint4 vah1 = *(const uint4*)(gAh + k0 + skA);
        const uint4 val0 = *(const uint4*)(gAl + k0);
        const uint4 val1 = *(const uint4*)(gAl + k0 + skA);
        const uint4 vbh0 = *(const uint4*)(gBh + k0);
        const uint4 vbh1 = *(const uint4*)(gBh + k0 + skB);
        const uint4 vbl0 = *(const uint4*)(gBl + k0);
        const uint4 vbl1 = *(const uint4*)(gBl + k0 + skB);
        __syncthreads();                      // previous iter's compute done
        *(uint4*)(swp)                    = vah0;
        *(uint4*)(swp + HOFF)             = vah1;
        *(uint4*)(swp + MOFF)             = val0;
        *(uint4*)(swp + MOFF + HOFF)      = val1;
        *(uint4*)(swp + 2 * MOFF)         = vbh0;
        *(uint4*)(swp + 2 * MOFF + HOFF)  = vbh1;
        *(uint4*)(swp + 3 * MOFF)         = vbl0;
        *(uint4*)(swp + 3 * MOFF + HOFF)  = vbl1;
        __syncthreads();                      // tiles visible

#pragma unroll
        for (int ks = 0; ks < 2; ++ks) {
            const int kk = ks * 16 + qc;

            uint32_t ah[2][4], al[2][4], bh[8][2], bl[8][2];
#pragma unroll
            for (int tm = 0; tm < 2; ++tm) {
                const int r = wm * 32 + tm * 16 + qr;
                ah[tm][0] = AHI_F(r,     kk);
                ah[tm][1] = AHI_F(r + 8, kk);
                ah[tm][2] = AHI_F(r,     kk + 8);
                ah[tm][3] = AHI_F(r + 8, kk + 8);
                al[tm][0] = ALO_F(r,     kk);
                al[tm][1] = ALO_F(r + 8, kk);
                al[tm][2] = ALO_F(r,     kk + 8);
                al[tm][3] = ALO_F(r + 8, kk + 8);
            }
#pragma unroll
            for (int tn = 0; tn < 8; ++tn) {
                const int r = wn * 64 + tn * 8 + qr;
                bh[tn][0] = BHI_F(r, kk);
                bh[tn][1] = BHI_F(r, kk + 8);
                bl[tn][0] = BLO_F(r, kk);
                bl[tn][1] = BLO_F(r, kk + 8);
            }
            // P1: Ahi*Bhi   P2: Ahi*Blo   P3: Alo*Bhi
#pragma unroll
            for (int tm = 0; tm < 2; ++tm)
#pragma unroll
                for (int tn = 0; tn < 8; ++tn) mma16(c[tm][tn], ah[tm], bh[tn]);
#pragma unroll
            for (int tm = 0; tm < 2; ++tm)
#pragma unroll
                for (int tn = 0; tn < 8; ++tn) mma16(c[tm][tn], ah[tm], bl[tn]);
#pragma unroll
            for (int tm = 0; tm < 2; ++tm)
#pragma unroll
                for (int tn = 0; tn < 8; ++tn) mma16(c[tm][tn], al[tm], bh[tn]);
        }
    }
#undef AHI_F
#undef ALO_F
#undef BHI_F
#undef BLO_F

    // epilogue (c fragment: c0,c1 = row qr cols qc..+1; c2,c3 = row qr+8)
    const int r0 = qr, cc = qc;
#pragma unroll
    for (int tm = 0; tm < 2; ++tm)
#pragma unroll
        for (int tn = 0; tn < 8; ++tn) {
            const int row = m0 + wm * 32 + tm * 16 + r0;
            const int col = n0 + wn * 64 + tn * 8 + cc;
#pragma unroll
            for (int hr = 0; hr < 2; ++hr) {
                const int rr = row + hr * 8;
                float v0 = c[tm][tn][hr * 2 + 0];
                float v1 = c[tm][tn][hr * 2 + 1];
                if (BIAS) { v0 += bias[col]; v1 += bias[col + 1]; }
                if (SPLIT_OUT) {
                    const u16 h0 = f2b(v0), h1 = f2b(v1);
                    const u16 l0 = f2b(v0 - b2f(h0)), l1 = f2b(v1 - b2f(h1));
                    *(uint32_t*)(Chi + (size_t)rr * ldc + col) =
                        ((uint32_t)h1 << 16) | (uint32_t)h0;
                    *(uint32_t*)(Clo + (size_t)rr * ldc + col) =
                        ((uint32_t)l1 << 16) | (uint32_t)l0;
                } else {
                    float2 v; v.x = v0; v.y = v1;
                    *(float2*)(C + (size_t)rr * ldc + col) = v;
                }
            }
        }
}

// ---------------- GEMM entry kernels (globals referenced in DEVICE code only) ----
__global__ __launch_bounds__(256) void k_qproj_t() {
    gemm3<true, false>(g_xhi, g_xlo, g_wqhi, g_wqlo,
                       DIM, DIM, DIM, 2 * DIM,
                       (float*)0, g_qhi, g_qlo, (const float*)0,
                       blockIdx.y * 128, blockIdx.x * 128);
}

__global__ __launch_bounds__(256) void k_dots_t() {
    const int z = blockIdx.z;
    const int b = z >> 4, h = (z >> 1) & 7, p = z & 1;
    const size_t aoff = (size_t)b * T_SEQ * (2 * DIM) + p * DIM + h * DHEAD;
    const size_t boff = (size_t)((h << 1) | p) * NKEYS * DHEAD;
    gemm3<false, false>(g_qhi + aoff, g_qlo + aoff, g_khi + boff, g_klo + boff,
                        DHEAD, 2 * DIM, DHEAD, NKEYS,
                        g_dots + (size_t)z * T_SEQ * NKEYS, (u16*)0, (u16*)0,
                        (const float*)0,
                        blockIdx.y * 128, blockIdx.x * 128);
}

__global__ __launch_bounds__(256) void k_outproj_t(const float* __restrict__ bo,
                                                   float* __restrict__ out) {
    gemm3<false, true>(g_ahi, g_alo, g_wohi, g_wolo,
                       DIM, DIM, DIM, DIM,
                       out, (u16*)0, (u16*)0, bo,
                       blockIdx.y * 128, blockIdx.x * 128);
}

// ---------------- split conversions ----------------
// Destination __device__ globals must be named in DEVICE code, never passed as
// host-side kernel args (host sees shadow addresses; ATS writes host memory).
__device__ __forceinline__ void split_one(const float* __restrict__ s,
                                          u16* __restrict__ hi,
                                          u16* __restrict__ lo, int n) {
    const int i = blockIdx.x * 256 + threadIdx.x;
    if (i < n) {
        const float v = s[i];
        const u16 a = f2b(v);
        hi[i] = a;
        lo[i] = f2b(v - b2f(a));
    }
}
__global__ void k_split_x (const float* __restrict__ s) { split_one(s, g_xhi,  g_xlo,  NBATCH * T_SEQ * DIM); }
__global__ void k_split_wq(const float* __restrict__ s) { split_one(s, g_wqhi, g_wqlo, 2 * DIM * DIM); }
__global__ void k_split_wo(const float* __restrict__ s) { split_one(s, g_wohi, g_wolo, DIM * DIM); }

// keys[h][n][p][d] -> g_khi/klo[(h*2+p)][n][d]
__global__ void k_split_keys(const float* __restrict__ keys) {
    const int i = blockIdx.x * 256 + threadIdx.x;
    if (i < 16 * NKEYS * DHEAD) {
        const int d = i & 127;
        const int n = (i >> 7) & 255;
        const int zk = i >> 15;
        const int h = zk >> 1, p = zk & 1;
        const float v = keys[(((size_t)(h * NKEYS + n) * 2 + p) << 7) + d];
        const u16 a = f2b(v);
        g_khi[i] = a;
        g_klo[i] = f2b(v - b2f(a));
    }
}

// ---------------- stage-1 top-32 of 256 per row (one warp/row) ----------------
__global__ __launch_bounds__(256) void k_topk1() {
    const int warp = threadIdx.x >> 5;
    const int lane = threadIdx.x & 31;
    const size_t row = (size_t)blockIdx.x * 8 + warp;
    const float* d = g_dots + row * NKEYS;
    const float NEGINF = __int_as_float(0xff800000);

    float v[8];
#pragma unroll
    for (int j = 0; j < 8; ++j) v[j] = d[j * 32 + lane];

    float* outs = g_s1s + row * TOPK;
    int*   outi = g_s1i + row * TOPK;

    for (int it = 0; it < TOPK; ++it) {
        float bv = NEGINF;
        int   bn = 1 << 30;
#pragma unroll
        for (int j = 0; j < 8; ++j) {
            const int n = j * 32 + lane;
            if (v[j] > bv) { bv = v[j]; bn = n; }
        }
#pragma unroll
        for (int off = 16; off > 0; off >>= 1) {
            const float ov = __shfl_xor_sync(0xffffffffu, bv, off);
            const int   on = __shfl_xor_sync(0xffffffffu, bn, off);
            if (ov > bv || (ov == bv && on < bn)) { bv = ov; bn = on; }
        }
        if (lane == 0) { outs[it] = bv; outi[it] = bn; }
        const int wl = bn & 31, wj = bn >> 5;
#pragma unroll
        for (int j = 0; j < 8; ++j)
            if (lane == wl && j == wj) v[j] = NEGINF;
    }
}

// ---------------- stage-2: one WARP per query, no smem, no block syncs ----------
// Candidates (Pareto set, 119) distributed 4 slots/lane; top-32 by iterative
// warp argmax (tie-break = smaller flattened candidate index, matching the old
// rank-select exactly); softmax + gather orders identical to old kernel ->
// bit-identical output.
__global__ __launch_bounds__(256) void k_stage2(const float* __restrict__ values) {
    const int wid  = threadIdx.x >> 5;
    const int lane = threadIdx.x & 31;
    const int tp = blockIdx.x * 8 + wid;       // 0..2047
    const int b  = blockIdx.y, h = blockIdx.z;
    const int i  = tp >> 1, p = tp & 1;
    const int z  = ((b * HEADS + h) << 1) + p;
    const size_t baseA = ((size_t)z * T_SEQ + i) * TOPK;
    const size_t baseB = ((size_t)z * T_SEQ + (T_SEQ / 2) + i) * TOPK;

    const float NEGINF = __int_as_float(0xff800000);
    const uint32_t FULL = 0xffffffffu;

    // per-lane sorted stage-1 entries
    const float sAv = g_s1s[baseA + lane];
    const int   iAv = g_s1i[baseA + lane];
    const float sBv = g_s1s[baseB + lane];
    const int   iBv = g_s1i[baseB + lane];

    // build candidate values: slot s holds candidate t = lane + 32*s
    float cv[4];
#pragma unroll
    for (int s = 0; s < 4; ++s) {
        const int t = lane + 32 * s;
        const u16 e = g_pareto[t];
        const int a = (e >> 8) & 31, c = e & 31;
        const float va = __shfl_sync(FULL, sAv, a);
        const float vb = __shfl_sync(FULL, sBv, c);
        cv[s] = (t < 119) ? (va + vb) : NEGINF;
    }

    // extract top-32 (descending); lane j ends holding rank-j value/index
    float myV = 0.f; int myI = 0;
    for (int it = 0; it < TOPK; ++it) {
        float bv = cv[0]; int bt = lane;
#pragma unroll
        for (int s = 1; s < 4; ++s)
            if (cv[s] > bv) { bv = cv[s]; bt = lane + 32 * s; }
#pragma unroll
        for (int off = 16; off > 0; off >>= 1) {
            const float ov = __shfl_xor_sync(FULL, bv, off);
            const int   ot = __shfl_xor_sync(FULL, bt, off);
            if (ov > bv || (ov == bv && ot < bt)) { bv = ov; bt = ot; }
        }
        // all lanes agree on winner (bv, bt); bt < 119 for real extractions
        const u16 e = g_pareto[bt];
        const int a = (e >> 8) & 31, c = e & 31;
        const int idx = __shfl_sync(FULL, iAv, a) * NKEYS + __shfl_sync(FULL, iBv, c);
        if (lane == it) { myV = bv; myI = idx; }
        if ((bt & 31) == lane) cv[bt >> 5] = NEGINF;   // clear winner slot
    }

    // softmax over sorted scores (lane 0 holds max) — same butterfly as before
    const float m = __shfl_sync(FULL, myV, 0);
    const float e = expf(myV - m);
    float ssum = e;
#pragma unroll
    for (int off = 16; off > 0; off >>= 1) ssum += __shfl_xor_sync(FULL, ssum, off);
    const float w = e / ssum;

    // gather: 32 weighted 512B rows, coalesced float4 per lane (cols 4l..4l+3)
    const float* V = values + (size_t)h * (NKEYS * NKEYS) * DHEAD;
    float a0 = 0.f, a1 = 0.f, a2 = 0.f, a3 = 0.f;
#pragma unroll
    for (int j = 0; j < TOPK; ++j) {
        const float wj = __shfl_sync(FULL, w, j);
        const int   vi = __shfl_sync(FULL, myI, j);
        const float4 vv = *(const float4*)(V + (size_t)vi * DHEAD + lane * 4);
        a0 = fmaf(wj, vv.x, a0);
        a1 = fmaf(wj, vv.y, a1);
        a2 = fmaf(wj, vv.z, a2);
        a3 = fmaf(wj, vv.w, a3);
    }

    const size_t oidx = ((size_t)(b * T_SEQ + tp)) * DIM + h * DHEAD + lane * 4;
    const u16 h0 = f2b(a0), h1 = f2b(a1), h2 = f2b(a2), h3 = f2b(a3);
    const u16 l0 = f2b(a0 - b2f(h0)), l1 = f2b(a1 - b2f(h1));
    const u16 l2 = f2b(a2 - b2f(h2)), l3 = f2b(a3 - b2f(h3));
    uint2 ph, pl;
    ph.x = ((uint32_t)h1 << 16) | h0;  ph.y = ((uint32_t)h3 << 16) | h2;
    pl.x = ((uint32_t)l1 << 16) | l0;  pl.y = ((uint32_t)l3 << 16) | l2;
    *(uint2*)(g_ahi + oidx) = ph;
    *(uint2*)(g_alo + oidx) = pl;
}

// ---------------- launch ----------------
extern "C" void kernel_launch(void* const* d_in, const int* in_sizes, int n_in,
                              void* d_out, int out_size)
{
    const float* x      = (const float*)d_in[0];
    const float* Wq     = (const float*)d_in[1];
    const float* keys   = (const float*)d_in[2];
    const float* values = (const float*)d_in[3];
    const float* Wo     = (const float*)d_in[4];
    const float* bo     = (const float*)d_in[5];
    float* out = (float*)d_out;

    const int nX  = NBATCH * T_SEQ * DIM;
    const int nWq = 2 * DIM * DIM;
    const int nWo = DIM * DIM;

    k_split_x <<<(nX  + 255) / 256, 256>>>(x);
    k_split_wq<<<(nWq + 255) / 256, 256>>>(Wq);
    k_split_wo<<<(nWo + 255) / 256, 256>>>(Wo);
    k_split_keys<<<(16 * NKEYS * DHEAD) / 256, 256>>>(keys);

    k_qproj_t<<<dim3(16, 32), 256>>>();
    k_dots_t <<<dim3(2, 16, 32), 256>>>();
    k_topk1  <<<(32 * T_SEQ) / 8, 256>>>();
    k_stage2 <<<dim3(T_SEQ / 8, NBATCH, HEADS), 256>>>(values);
    k_outproj_t<<<dim3(8, 32), 256>>>(bo, out);
}